// round 6
// baseline (speedup 1.0000x reference)
#include <cuda_runtime.h>
#include <cuda_fp16.h>

#define CDIM 64
#define KK   25
#define KO   (CDIM * KK)   // 1600
#define MAXN 50000
#define MAXE 800000

typedef unsigned long long ull;
typedef unsigned int uint32;

// ---------------- scratch (static device globals; no allocation) ------------
__device__ __half g_xW[(size_t)MAXN * KO];   // 160 MB (fp16), reused by both layers
__device__ float  g_x1[(size_t)MAXN * CDIM];
__device__ float  g_x2[(size_t)MAXN * CDIM];
__device__ __half g_x16[(size_t)MAXN * CDIM];  // fp16 input for HMMA gemm
__device__ __half g_W16[KK * CDIM * CDIM];     // fp16 weights for current layer
__device__ float2 g_pm[(size_t)MAXN * 32];     // partial max scratch (12.8MB)
__device__ int    g_counts[2 * MAXN];
__device__ int    g_rowptr[2 * MAXN + 1];
__device__ int    g_cursor[2 * MAXN];
__device__ int2   g_sw[MAXE];      // {src, packed wi bytes}
__device__ float4 g_basis[MAXE];

// ---------------- packed f32x2 helpers (final gemm) --------------------------
__device__ __forceinline__ float2 ffma2(float2 a, ull b, float2 c) {
    ull au = *reinterpret_cast<ull*>(&a);
    ull cu = *reinterpret_cast<ull*>(&c);
    ull du;
    asm("fma.rn.f32x2 %0, %1, %2, %3;" : "=l"(du) : "l"(au), "l"(b), "l"(cu));
    return *reinterpret_cast<float2*>(&du);
}
__device__ __forceinline__ ull dup2(float b) {
    ull r;
    asm("mov.b64 %0, {%1, %1};" : "=l"(r) : "f"(b));
    return r;
}

// ---------------- mma / ldmatrix helpers -------------------------------------
__device__ __forceinline__ void mma16816(float c[4], const uint32 a[4],
                                         uint32 b0, uint32 b1) {
    asm volatile("mma.sync.aligned.m16n8k16.row.col.f32.f16.f16.f32 "
                 "{%0,%1,%2,%3}, {%4,%5,%6,%7}, {%8,%9}, {%0,%1,%2,%3};"
                 : "+f"(c[0]), "+f"(c[1]), "+f"(c[2]), "+f"(c[3])
                 : "r"(a[0]), "r"(a[1]), "r"(a[2]), "r"(a[3]), "r"(b0), "r"(b1));
}
__device__ __forceinline__ void ldsm_x4(uint32 r[4], uint32 addr) {
    asm volatile("ldmatrix.sync.aligned.m8n8.x4.shared.b16 {%0,%1,%2,%3}, [%4];"
                 : "=r"(r[0]), "=r"(r[1]), "=r"(r[2]), "=r"(r[3]) : "r"(addr));
}
__device__ __forceinline__ void ldsm_x2t(uint32& r0, uint32& r1, uint32 addr) {
    asm volatile("ldmatrix.sync.aligned.m8n8.x2.trans.shared.b16 {%0,%1}, [%2];"
                 : "=r"(r0), "=r"(r1) : "r"(addr));
}

// L2-only half2 load (skip L1 allocation — gathers have no intra-SM reuse)
__device__ __forceinline__ __half2 ldcg_h2(const __half2* p) {
    uint32 v;
    asm volatile("ld.global.cg.b32 %0, [%1];" : "=r"(v) : "l"(p));
    return *reinterpret_cast<__half2*>(&v);
}

// ---------------- fp32 -> fp16 conversion ------------------------------------
__global__ void f2h_kernel(const float* __restrict__ in, __half* __restrict__ out,
                           int n4) {
    int i = blockIdx.x * blockDim.x + threadIdx.x;
    if (i < n4) {
        float4 v = ((const float4*)in)[i];
        union { uint2 u; __half2 h[2]; } pk;
        pk.h[0] = __floats2half2_rn(v.x, v.y);
        pk.h[1] = __floats2half2_rn(v.z, v.w);
        ((uint2*)out)[i] = pk.u;
    }
}

// ---------------- CSR build (segments: 2*dst + src_chunk) --------------------
__global__ void zero_counts_kernel(int M) {
    int i = blockIdx.x * blockDim.x + threadIdx.x;
    if (i < M) g_counts[i] = 0;
}

__global__ void count_kernel(const int* __restrict__ ei, int E, int half) {
    int e = blockIdx.x * blockDim.x + threadIdx.x;
    if (e < E) {
        int seg = ei[E + e] * 2 + (ei[e] >= half ? 1 : 0);
        atomicAdd(&g_counts[seg], 1);
    }
}

__global__ void scan_kernel(int M) {
    __shared__ int warp_off[32];
    __shared__ int s_carry;
    int tid  = threadIdx.x;
    int lane = tid & 31;
    int wid  = tid >> 5;
    if (tid == 0) s_carry = 0;
    __syncthreads();
    for (int base = 0; base < M; base += 1024) {
        int i = base + tid;
        int v = (i < M) ? g_counts[i] : 0;
        int incl = v;
        #pragma unroll
        for (int off = 1; off < 32; off <<= 1) {
            int t = __shfl_up_sync(0xffffffffu, incl, off);
            if (lane >= off) incl += t;
        }
        if (lane == 31) warp_off[wid] = incl;
        __syncthreads();
        if (wid == 0) {
            int s = warp_off[lane];
            int si = s;
            #pragma unroll
            for (int off = 1; off < 32; off <<= 1) {
                int t = __shfl_up_sync(0xffffffffu, si, off);
                if (lane >= off) si += t;
            }
            warp_off[lane] = si - s;
        }
        __syncthreads();
        int excl = incl - v + warp_off[wid] + s_carry;
        if (i < M) { g_rowptr[i] = excl; g_cursor[i] = excl; }
        __syncthreads();
        if (tid == 1023) s_carry = excl + v;
        __syncthreads();
    }
    if (tid == 0) g_rowptr[M] = s_carry;
}

__global__ void scatter_kernel(const int* __restrict__ ei,
                               const float* __restrict__ attr, int E, int half) {
    int e = blockIdx.x * blockDim.x + threadIdx.x;
    if (e >= E) return;
    int src = ei[e];
    int dst = ei[E + e];

    float p0 = attr[2 * e + 0];
    float p1 = attr[2 * e + 1];
    float v0 = p0 * 4.0f, v1 = p1 * 4.0f;
    float l0 = floorf(v0), l1 = floorf(v1);
    float f0 = v0 - l0,    f1 = v1 - l1;
    int i0 = (int)l0, i1 = (int)l1;
    int i00 = min(max(i0, 0), 4);
    int i01 = min(max(i0 + 1, 0), 4);
    int i10 = min(max(i1, 0), 4);
    int i11 = min(max(i1 + 1, 0), 4);

    float4 b;
    b.x = (1.0f - f0) * (1.0f - f1);
    b.y = (1.0f - f0) * f1;
    b.z = f0 * (1.0f - f1);
    b.w = f0 * f1;
    int wp = (i00 + 5 * i10)
           | ((i00 + 5 * i11) << 8)
           | ((i01 + 5 * i10) << 16)
           | ((i01 + 5 * i11) << 24);

    int seg = dst * 2 + (src >= half ? 1 : 0);
    int pos = atomicAdd(&g_cursor[seg], 1);
    g_sw[pos]    = make_int2(src, wp);
    g_basis[pos] = b;
}

// ---------------- HMMA GEMM: xW[n, k*64+o] = sum_i X16[n,i] * W16[k,i,o] -----
__global__ void gemm_xw_hmma(const __half* __restrict__ X16,
                             const __half* __restrict__ W16, int N) {
    __shared__ __half xs[128][72];
    __shared__ __half ws[64][72];
    __shared__ __half os[128][72];
    int k    = blockIdx.y;
    int row0 = blockIdx.x * 128;
    int tid  = threadIdx.x;

    #pragma unroll
    for (int t = tid; t < 1024; t += 128) {
        int r = t >> 3, c8 = (t & 7) * 8;
        int gr = row0 + r;
        uint4 v = make_uint4(0, 0, 0, 0);
        if (gr < N) v = *(const uint4*)&X16[(size_t)gr * CDIM + c8];
        *(uint4*)&xs[r][c8] = v;
    }
    #pragma unroll
    for (int t = tid; t < 512; t += 128) {
        int r = t >> 3, c8 = (t & 7) * 8;
        *(uint4*)&ws[r][c8] = *(const uint4*)&W16[k * 4096 + r * 64 + c8];
    }
    __syncthreads();

    int warp = tid >> 5, lane = tid & 31;
    int m_base = warp * 32;
    float c[2][8][4];
    #pragma unroll
    for (int mt = 0; mt < 2; ++mt)
        #pragma unroll
        for (int nt = 0; nt < 8; ++nt)
            #pragma unroll
            for (int j = 0; j < 4; ++j) c[mt][nt][j] = 0.f;

    #pragma unroll
    for (int kt = 0; kt < 4; ++kt) {
        int kb = kt * 16;
        uint32 a[2][4];
        #pragma unroll
        for (int mt = 0; mt < 2; ++mt) {
            uint32 addr = (uint32)__cvta_generic_to_shared(
                &xs[m_base + mt * 16 + (lane & 15)][kb + (lane >> 4) * 8]);
            ldsm_x4(a[mt], addr);
        }
        #pragma unroll
        for (int nt = 0; nt < 8; ++nt) {
            uint32 baddr = (uint32)__cvta_generic_to_shared(
                &ws[kb + (lane & 15)][nt * 8]);
            uint32 b0, b1;
            ldsm_x2t(b0, b1, baddr);
            mma16816(c[0][nt], a[0], b0, b1);
            mma16816(c[1][nt], a[1], b0, b1);
        }
    }

    int fr = lane >> 2;
    int fc = 2 * (lane & 3);
    #pragma unroll
    for (int mt = 0; mt < 2; ++mt) {
        #pragma unroll
        for (int nt = 0; nt < 8; ++nt) {
            *(__half2*)&os[m_base + mt * 16 + fr][nt * 8 + fc] =
                __floats2half2_rn(c[mt][nt][0], c[mt][nt][1]);
            *(__half2*)&os[m_base + mt * 16 + 8 + fr][nt * 8 + fc] =
                __floats2half2_rn(c[mt][nt][2], c[mt][nt][3]);
        }
    }
    __syncwarp();
    #pragma unroll
    for (int it = 0; it < 8; ++it) {
        int r  = m_base + it * 4 + (lane >> 3);
        int gr = row0 + r;
        if (gr < N) {
            uint4 v = *(uint4*)&os[r][(lane & 7) * 8];
            *(uint4*)&g_xW[(size_t)gr * KO + k * 64 + (lane & 7) * 8] = v;
        }
    }
}

// ---------------- aggregation: chunked two-pass segment max -----------------
__device__ __forceinline__ float2 edge_msg(int e, int lane) {
    int2   sw = g_sw[e];
    float4 b  = g_basis[e];
    const __half2* p = (const __half2*)(g_xW + (size_t)sw.x * KO) + lane;
    unsigned w = (unsigned)sw.y;
    __half2 a0 = ldcg_h2(p + ((w      ) & 255) * 32);
    __half2 a1 = ldcg_h2(p + ((w >>  8) & 255) * 32);
    __half2 a2 = ldcg_h2(p + ((w >> 16) & 255) * 32);
    __half2 a3 = ldcg_h2(p + ((w >> 24) & 255) * 32);
    float2 f, v;
    f = __half22float2(a0); v.x = b.x * f.x;           v.y = b.x * f.y;
    f = __half22float2(a1); v.x = fmaf(b.y, f.x, v.x); v.y = fmaf(b.y, f.y, v.y);
    f = __half22float2(a2); v.x = fmaf(b.z, f.x, v.x); v.y = fmaf(b.z, f.y, v.y);
    f = __half22float2(a3); v.x = fmaf(b.w, f.x, v.x); v.y = fmaf(b.w, f.y, v.y);
    return v;
}

// run a 4-edge-batched max over [beg, end), folding into m
__device__ __forceinline__ void seg_max(int beg, int end, int lane, float2& m) {
    const float NEG = __int_as_float(0xff800000);
    float2 m1 = make_float2(NEG, NEG);
    float2 m2 = make_float2(NEG, NEG);
    float2 m3 = make_float2(NEG, NEG);
    int e = beg;
    for (; e + 3 < end; e += 4) {
        int2   sw[4];
        float4 bb[4];
        #pragma unroll
        for (int j = 0; j < 4; ++j) { sw[j] = g_sw[e + j]; bb[j] = g_basis[e + j]; }
        __half2 h[4][4];
        #pragma unroll
        for (int j = 0; j < 4; ++j) {
            const __half2* p = (const __half2*)(g_xW + (size_t)sw[j].x * KO) + lane;
            unsigned w = (unsigned)sw[j].y;
            h[j][0] = ldcg_h2(p + ((w      ) & 255) * 32);
            h[j][1] = ldcg_h2(p + ((w >>  8) & 255) * 32);
            h[j][2] = ldcg_h2(p + ((w >> 16) & 255) * 32);
            h[j][3] = ldcg_h2(p + ((w >> 24) & 255) * 32);
        }
        #pragma unroll
        for (int j = 0; j < 4; ++j) {
            float4 b = bb[j];
            float2 f, v;
            f = __half22float2(h[j][0]); v.x = b.x * f.x;           v.y = b.x * f.y;
            f = __half22float2(h[j][1]); v.x = fmaf(b.y, f.x, v.x); v.y = fmaf(b.y, f.y, v.y);
            f = __half22float2(h[j][2]); v.x = fmaf(b.z, f.x, v.x); v.y = fmaf(b.z, f.y, v.y);
            f = __half22float2(h[j][3]); v.x = fmaf(b.w, f.x, v.x); v.y = fmaf(b.w, f.y, v.y);
            if (j == 0) { m.x  = fmaxf(m.x,  v.x); m.y  = fmaxf(m.y,  v.y); }
            if (j == 1) { m1.x = fmaxf(m1.x, v.x); m1.y = fmaxf(m1.y, v.y); }
            if (j == 2) { m2.x = fmaxf(m2.x, v.x); m2.y = fmaxf(m2.y, v.y); }
            if (j == 3) { m3.x = fmaxf(m3.x, v.x); m3.y = fmaxf(m3.y, v.y); }
        }
    }
    for (; e < end; ++e) {
        float2 v = edge_msg(e, lane);
        m.x = fmaxf(m.x, v.x); m.y = fmaxf(m.y, v.y);
    }
    m.x = fmaxf(fmaxf(m.x, m1.x), fmaxf(m2.x, m3.x));
    m.y = fmaxf(fmaxf(m.y, m1.y), fmaxf(m2.y, m3.y));
}

// pass A: chunk-1 edges (src >= half; gathers land in upper 80MB of g_xW,
// which is still L2-warm from the gemm) -> partial max to g_pm
__global__ void __launch_bounds__(256, 2)
agg_pass_a(int N) {
    int wib  = threadIdx.x >> 5;
    int lane = threadIdx.x & 31;
    int n    = blockIdx.x * 8 + wib;
    if (n >= N) return;
    const float NEG = __int_as_float(0xff800000);
    float2 m = make_float2(NEG, NEG);
    seg_max(g_rowptr[2 * n + 1], g_rowptr[2 * n + 2], lane, m);
    g_pm[(size_t)n * 32 + lane] = m;
}

// pass B: chunk-0 edges (src < half; 80MB set, L2-resident) + root+bias+relu
__global__ void __launch_bounds__(256, 2)
agg_pass_b(const float* __restrict__ xin,
           const float* __restrict__ root,
           const float* __restrict__ bias,
           float* __restrict__ xout,
           __half* __restrict__ xout16, int N) {
    __shared__ float sx[8][64];
    int wib  = threadIdx.x >> 5;
    int lane = threadIdx.x & 31;
    int n    = blockIdx.x * 8 + wib;

    for (int t = threadIdx.x; t < 8 * 64; t += 256) {
        int r = t >> 6, c = t & 63;
        int gn = blockIdx.x * 8 + r;
        sx[r][c] = (gn < N) ? xin[(size_t)gn * CDIM + c] : 0.f;
    }
    __syncthreads();
    if (n >= N) return;

    int c0 = lane * 2;
    float2 r2;
    r2.x = bias[c0];
    r2.y = bias[c0 + 1];
    #pragma unroll
    for (int i = 0; i < CDIM; ++i) {
        float  xi = sx[wib][i];
        float2 rv = *(const float2*)&root[i * CDIM + c0];
        r2.x = fmaf(xi, rv.x, r2.x);
        r2.y = fmaf(xi, rv.y, r2.y);
    }

    int beg0 = g_rowptr[2 * n];
    int end0 = g_rowptr[2 * n + 1];
    int end1 = g_rowptr[2 * n + 2];
    float2 m = g_pm[(size_t)n * 32 + lane];
    seg_max(beg0, end0, lane, m);

    bool has = (beg0 != end1);  // any edges in either chunk
    float2 agg = has ? m : make_float2(0.f, 0.f);
    float2 o = make_float2(fmaxf(agg.x + r2.x, 0.f), fmaxf(agg.y + r2.y, 0.f));
    *(float2*)&xout[(size_t)n * CDIM + c0] = o;
    *(__half2*)&xout16[(size_t)n * CDIM + c0] = __floats2half2_rn(o.x, o.y);
}

// ---------------- final: out = [x | x1 | x2] @ fw + fb ----------------------
__global__ void final_gemm_kernel(const float* __restrict__ x,
                                  const float* __restrict__ fw,
                                  const float* __restrict__ fb,
                                  float* __restrict__ out, int N) {
    __shared__ float2 As2[64][64];
    __shared__ float  Bs[64][64];
    int row0 = blockIdx.x * 128;
    int tid  = threadIdx.x;
    int tx = tid & 7, ty = tid >> 3;

    float2 acc[4][8];
    #pragma unroll
    for (int rp = 0; rp < 4; ++rp)
        #pragma unroll
        for (int c = 0; c < 8; ++c) acc[rp][c] = make_float2(0.f, 0.f);

    for (int ch = 0; ch < 3; ++ch) {
        const float* S = (ch == 0) ? x : (ch == 1) ? g_x1 : g_x2;
        __syncthreads();
        #pragma unroll
        for (int t = tid; t < 128 * 16; t += 128) {
            int r = t >> 4, c4 = (t & 15) * 4;
            int gr = row0 + r;
            float4 v = make_float4(0.f, 0.f, 0.f, 0.f);
            if (gr < N) v = *(const float4*)&S[(size_t)gr * CDIM + c4];
            float* dstp0 = (float*)&As2[r >> 1][c4 + 0];
            int l = r & 1;
            dstp0[l]     = v.x;
            dstp0[2 + l] = v.y;
            dstp0[4 + l] = v.z;
            dstp0[6 + l] = v.w;
        }
        #pragma unroll
        for (int t = tid; t < 64 * 16; t += 128) {
            int r = t >> 4, c4 = (t & 15) * 4;
            *(float4*)&Bs[r][c4] = *(const float4*)&fw[ch * 4096 + r * 64 + c4];
        }
        __syncthreads();

        #pragma unroll 16
        for (int i = 0; i < 64; ++i) {
            float2 ap[4];
            #pragma unroll
            for (int rp = 0; rp < 4; ++rp) ap[rp] = As2[ty * 4 + rp][i];
            float4 b0 = *(const float4*)&Bs[i][tx * 8];
            float4 b1 = *(const float4*)&Bs[i][tx * 8 + 4];
            ull bb[8];
            bb[0] = dup2(b0.x); bb[1] = dup2(b0.y); bb[2] = dup2(b0.z); bb[3] = dup2(b0.w);
            bb[4] = dup2(b1.x); bb[5] = dup2(b1.y); bb[6] = dup2(b1.z); bb[7] = dup2(b1.w);
            #pragma unroll
            for (int rp = 0; rp < 4; ++rp)
                #pragma unroll
                for (int c = 0; c < 8; ++c)
                    acc[rp][c] = ffma2(ap[rp], bb[c], acc[rp][c]);
        }
    }

    float4 fb0 = *(const float4*)&fb[tx * 8];
    float4 fb1 = *(const float4*)&fb[tx * 8 + 4];
    #pragma unroll
    for (int rp = 0; rp < 4; ++rp) {
        int r0 = row0 + ty * 8 + rp * 2;
        if (r0 < N) {
            float4 v0 = make_float4(acc[rp][0].x + fb0.x, acc[rp][1].x + fb0.y,
                                    acc[rp][2].x + fb0.z, acc[rp][3].x + fb0.w);
            float4 v1 = make_float4(acc[rp][4].x + fb1.x, acc[rp][5].x + fb1.y,
                                    acc[rp][6].x + fb1.z, acc[rp][7].x + fb1.w);
            *(float4*)&out[(size_t)r0 * CDIM + tx * 8]     = v0;
            *(float4*)&out[(size_t)r0 * CDIM + tx * 8 + 4] = v1;
        }
        if (r0 + 1 < N) {
            float4 v0 = make_float4(acc[rp][0].y + fb0.x, acc[rp][1].y + fb0.y,
                                    acc[rp][2].y + fb0.z, acc[rp][3].y + fb0.w);
            float4 v1 = make_float4(acc[rp][4].y + fb1.x, acc[rp][5].y + fb1.y,
                                    acc[rp][6].y + fb1.z, acc[rp][7].y + fb1.w);
            *(float4*)&out[(size_t)(r0 + 1) * CDIM + tx * 8]     = v0;
            *(float4*)&out[(size_t)(r0 + 1) * CDIM + tx * 8 + 4] = v1;
        }
    }
}

// ---------------- launch -----------------------------------------------------
extern "C" void kernel_launch(void* const* d_in, const int* in_sizes, int n_in,
                              void* d_out, int out_size) {
    const float* x     = (const float*)d_in[0];
    const int*   ei    = (const int*)  d_in[1];
    const float* attr  = (const float*)d_in[2];
    const float* W1    = (const float*)d_in[3];
    const float* root1 = (const float*)d_in[4];
    const float* b1    = (const float*)d_in[5];
    const float* W2    = (const float*)d_in[6];
    const float* root2 = (const float*)d_in[7];
    const float* b2    = (const float*)d_in[8];
    const float* fw    = (const float*)d_in[9];
    const float* fb    = (const float*)d_in[10];
    float* out = (float*)d_out;

    int N = in_sizes[0] / CDIM;
    int E = in_sizes[1] / 2;
    if (N > MAXN) N = MAXN;
    if (E > MAXE) E = MAXE;
    int half = N / 2;
    int M = 2 * N;  // segments

    float *px1 = nullptr, *px2 = nullptr;
    __half *px16 = nullptr, *pw16 = nullptr;
    cudaGetSymbolAddress((void**)&px1, g_x1);
    cudaGetSymbolAddress((void**)&px2, g_x2);
    cudaGetSymbolAddress((void**)&px16, g_x16);
    cudaGetSymbolAddress((void**)&pw16, g_W16);

    int eb = (E + 255) / 256;
    int mb = (M + 255) / 256;
    dim3 ggrid((N + 127) / 128, KK);
    int ab = (N + 7) / 8;

    int xq = N * CDIM / 4;
    int wq = KK * CDIM * CDIM / 4;

    // (launch order puts gemm #1 in the profiled slot)
    f2h_kernel<<<(xq + 255) / 256, 256>>>(x, px16, xq);        // 1
    f2h_kernel<<<(wq + 255) / 256, 256>>>(W1, pw16, wq);       // 2
    zero_counts_kernel<<<mb, 256>>>(M);                        // 3
    gemm_xw_hmma<<<ggrid, 128>>>(px16, pw16, N);               // 4 <- profiled
    count_kernel<<<eb, 256>>>(ei, E, half);                    // 5
    scan_kernel<<<1, 1024>>>(M);                               // 6
    scatter_kernel<<<eb, 256>>>(ei, attr, E, half);            // 7

    // layer 1 aggregation (chunk-1 pass first: L2 still warm from gemm tail)
    agg_pass_a<<<ab, 256>>>(N);                                // 8
    agg_pass_b<<<ab, 256>>>(x, root1, b1, px1, px16, N);       // 9

    // layer 2
    f2h_kernel<<<(wq + 255) / 256, 256>>>(W2, pw16, wq);       // 10
    gemm_xw_hmma<<<ggrid, 128>>>(px16, pw16, N);               // 11
    agg_pass_a<<<ab, 256>>>(N);                                // 12
    agg_pass_b<<<ab, 256>>>(px1, root2, b2, px2, px16, N);     // 13

    // final projection
    final_gemm_kernel<<<(N + 127) / 128, 128>>>(x, fw, fb, out, N);  // 14
}

// round 7
// speedup vs baseline: 1.1842x; 1.1842x over previous
#include <cuda_runtime.h>
#include <cuda_fp16.h>

#define CDIM 64
#define KK   25
#define KO   (CDIM * KK)   // 1600
#define MAXN 50000
#define MAXE 800000

typedef unsigned long long ull;
typedef unsigned int uint32;

// ---------------- scratch (static device globals; no allocation) ------------
__device__ __half g_xW[(size_t)MAXN * KO];   // 160 MB (fp16), reused by both layers
__device__ float  g_x1[(size_t)MAXN * CDIM];
__device__ float  g_x2[(size_t)MAXN * CDIM];
__device__ __half g_x16[(size_t)MAXN * CDIM];  // fp16 input for HMMA gemm
__device__ __half g_W16[KK * CDIM * CDIM];     // fp16 weights for current layer
__device__ int    g_counts[MAXN];
__device__ int    g_rowptr[MAXN + 1];
__device__ int    g_cursor[MAXN];
__device__ int2   g_sw[MAXE];      // {src, packed wi bytes}
__device__ float4 g_basis[MAXE];

// ---------------- packed f32x2 helpers (final gemm) --------------------------
__device__ __forceinline__ float2 ffma2(float2 a, ull b, float2 c) {
    ull au = *reinterpret_cast<ull*>(&a);
    ull cu = *reinterpret_cast<ull*>(&c);
    ull du;
    asm("fma.rn.f32x2 %0, %1, %2, %3;" : "=l"(du) : "l"(au), "l"(b), "l"(cu));
    return *reinterpret_cast<float2*>(&du);
}
__device__ __forceinline__ ull dup2(float b) {
    ull r;
    asm("mov.b64 %0, {%1, %1};" : "=l"(r) : "f"(b));
    return r;
}

// ---------------- mma / ldmatrix helpers -------------------------------------
__device__ __forceinline__ void mma16816(float c[4], const uint32 a[4],
                                         uint32 b0, uint32 b1) {
    asm volatile("mma.sync.aligned.m16n8k16.row.col.f32.f16.f16.f32 "
                 "{%0,%1,%2,%3}, {%4,%5,%6,%7}, {%8,%9}, {%0,%1,%2,%3};"
                 : "+f"(c[0]), "+f"(c[1]), "+f"(c[2]), "+f"(c[3])
                 : "r"(a[0]), "r"(a[1]), "r"(a[2]), "r"(a[3]), "r"(b0), "r"(b1));
}
__device__ __forceinline__ void ldsm_x4(uint32 r[4], uint32 addr) {
    asm volatile("ldmatrix.sync.aligned.m8n8.x4.shared.b16 {%0,%1,%2,%3}, [%4];"
                 : "=r"(r[0]), "=r"(r[1]), "=r"(r[2]), "=r"(r[3]) : "r"(addr));
}
__device__ __forceinline__ void ldsm_x2t(uint32& r0, uint32& r1, uint32 addr) {
    asm volatile("ldmatrix.sync.aligned.m8n8.x2.trans.shared.b16 {%0,%1}, [%2];"
                 : "=r"(r0), "=r"(r1) : "r"(addr));
}

// L2-only half2 load (gathers have no intra-SM reuse)
__device__ __forceinline__ __half2 ldcg_h2(const __half2* p) {
    uint32 v;
    asm volatile("ld.global.cg.b32 %0, [%1];" : "=r"(v) : "l"(p));
    return *reinterpret_cast<__half2*>(&v);
}

// ---------------- fp32 -> fp16 conversion ------------------------------------
__global__ void f2h_kernel(const float* __restrict__ in, __half* __restrict__ out,
                           int n4) {
    int i = blockIdx.x * blockDim.x + threadIdx.x;
    if (i < n4) {
        float4 v = ((const float4*)in)[i];
        union { uint2 u; __half2 h[2]; } pk;
        pk.h[0] = __floats2half2_rn(v.x, v.y);
        pk.h[1] = __floats2half2_rn(v.z, v.w);
        ((uint2*)out)[i] = pk.u;
    }
}

// ---------------- CSR build -------------------------------------------------
__global__ void zero_counts_kernel(int N) {
    int i = blockIdx.x * blockDim.x + threadIdx.x;
    if (i < N) g_counts[i] = 0;
}

__global__ void count_kernel(const int* __restrict__ ei, int E) {
    int e = blockIdx.x * blockDim.x + threadIdx.x;
    if (e < E) atomicAdd(&g_counts[ei[E + e]], 1);
}

__global__ void scan_kernel(int N) {
    __shared__ int warp_off[32];
    __shared__ int s_carry;
    int tid  = threadIdx.x;
    int lane = tid & 31;
    int wid  = tid >> 5;
    if (tid == 0) s_carry = 0;
    __syncthreads();
    for (int base = 0; base < N; base += 1024) {
        int i = base + tid;
        int v = (i < N) ? g_counts[i] : 0;
        int incl = v;
        #pragma unroll
        for (int off = 1; off < 32; off <<= 1) {
            int t = __shfl_up_sync(0xffffffffu, incl, off);
            if (lane >= off) incl += t;
        }
        if (lane == 31) warp_off[wid] = incl;
        __syncthreads();
        if (wid == 0) {
            int s = warp_off[lane];
            int si = s;
            #pragma unroll
            for (int off = 1; off < 32; off <<= 1) {
                int t = __shfl_up_sync(0xffffffffu, si, off);
                if (lane >= off) si += t;
            }
            warp_off[lane] = si - s;
        }
        __syncthreads();
        int excl = incl - v + warp_off[wid] + s_carry;
        if (i < N) { g_rowptr[i] = excl; g_cursor[i] = excl; }
        __syncthreads();
        if (tid == 1023) s_carry = excl + v;
        __syncthreads();
    }
    if (tid == 0) g_rowptr[N] = s_carry;
}

__global__ void scatter_kernel(const int* __restrict__ ei,
                               const float* __restrict__ attr, int E) {
    int e = blockIdx.x * blockDim.x + threadIdx.x;
    if (e >= E) return;
    int src = ei[e];
    int dst = ei[E + e];

    float p0 = attr[2 * e + 0];
    float p1 = attr[2 * e + 1];
    float v0 = p0 * 4.0f, v1 = p1 * 4.0f;
    float l0 = floorf(v0), l1 = floorf(v1);
    float f0 = v0 - l0,    f1 = v1 - l1;
    int i0 = (int)l0, i1 = (int)l1;
    int i00 = min(max(i0, 0), 4);
    int i01 = min(max(i0 + 1, 0), 4);
    int i10 = min(max(i1, 0), 4);
    int i11 = min(max(i1 + 1, 0), 4);

    float4 b;
    b.x = (1.0f - f0) * (1.0f - f1);
    b.y = (1.0f - f0) * f1;
    b.z = f0 * (1.0f - f1);
    b.w = f0 * f1;
    int wp = (i00 + 5 * i10)
           | ((i00 + 5 * i11) << 8)
           | ((i01 + 5 * i10) << 16)
           | ((i01 + 5 * i11) << 24);

    int pos = atomicAdd(&g_cursor[dst], 1);
    g_sw[pos]    = make_int2(src, wp);
    g_basis[pos] = b;
}

// ---------------- HMMA GEMM, k-batched ---------------------------------------
// grid (ceil(N/128), 5): block handles 128 rows x 5 consecutive k's.
// X tile staged once; A fragments register-resident across all 5 k's.
#define KBATCH 5
__global__ void __launch_bounds__(128, 4)
gemm_xw_hmma(const __half* __restrict__ X16,
             const __half* __restrict__ W16, int N) {
    __shared__ __half xs[128][72];
    __shared__ __half ws[64][72];
    int row0 = blockIdx.x * 128;
    int k0   = blockIdx.y * KBATCH;
    int tid  = threadIdx.x;

    // stage X tile (128x64 halfs)
    #pragma unroll
    for (int t = tid; t < 1024; t += 128) {
        int r = t >> 3, c8 = (t & 7) * 8;
        int gr = row0 + r;
        uint4 v = make_uint4(0, 0, 0, 0);
        if (gr < N) v = *(const uint4*)&X16[(size_t)gr * CDIM + c8];
        *(uint4*)&xs[r][c8] = v;
    }
    __syncthreads();

    int warp = tid >> 5, lane = tid & 31;
    int m_base = warp * 32;

    // A fragments: 32 rows x 64 k per warp, loaded ONCE
    uint32 a[2][4][4];   // [mtile][kstep][frag]
    #pragma unroll
    for (int mt = 0; mt < 2; ++mt)
        #pragma unroll
        for (int kt = 0; kt < 4; ++kt) {
            uint32 addr = (uint32)__cvta_generic_to_shared(
                &xs[m_base + mt * 16 + (lane & 15)][kt * 16 + (lane >> 4) * 8]);
            ldsm_x4(a[mt][kt], addr);
        }

    for (int kk = 0; kk < KBATCH; ++kk) {
        int k = k0 + kk;
        __syncthreads();   // previous iter's ws reads done
        #pragma unroll
        for (int t = tid; t < 512; t += 128) {
            int r = t >> 3, c8 = (t & 7) * 8;
            *(uint4*)&ws[r][c8] = *(const uint4*)&W16[k * 4096 + r * 64 + c8];
        }
        __syncthreads();

        float c[2][8][4];
        #pragma unroll
        for (int mt = 0; mt < 2; ++mt)
            #pragma unroll
            for (int nt = 0; nt < 8; ++nt)
                #pragma unroll
                for (int j = 0; j < 4; ++j) c[mt][nt][j] = 0.f;

        #pragma unroll
        for (int kt = 0; kt < 4; ++kt) {
            #pragma unroll
            for (int nt = 0; nt < 8; ++nt) {
                uint32 baddr = (uint32)__cvta_generic_to_shared(
                    &ws[kt * 16 + (lane & 15)][nt * 8]);
                uint32 b0, b1;
                ldsm_x2t(b0, b1, baddr);
                mma16816(c[0][nt], a[0][kt], b0, b1);
                mma16816(c[1][nt], a[1][kt], b0, b1);
            }
        }

        // direct half2 stores
        int colq = 2 * (lane & 3);
        #pragma unroll
        for (int mt = 0; mt < 2; ++mt) {
            int row = row0 + m_base + mt * 16 + (lane >> 2);
            #pragma unroll
            for (int nt = 0; nt < 8; ++nt) {
                int col = nt * 8 + colq;
                if (row < N) {
                    __half2 h = __floats2half2_rn(c[mt][nt][0], c[mt][nt][1]);
                    *(__half2*)&g_xW[(size_t)row * KO + k * 64 + col] = h;
                }
                if (row + 8 < N) {
                    __half2 h = __floats2half2_rn(c[mt][nt][2], c[mt][nt][3]);
                    *(__half2*)&g_xW[(size_t)(row + 8) * KO + k * 64 + col] = h;
                }
            }
        }
    }
}

// ---------------- per-node aggregation: warp per node, half2 gathers --------
__device__ __forceinline__ float2 edge_msg(int e, int lane) {
    int2   sw = g_sw[e];
    float4 b  = g_basis[e];
    const __half2* p = (const __half2*)(g_xW + (size_t)sw.x * KO) + lane;
    unsigned w = (unsigned)sw.y;
    __half2 a0 = ldcg_h2(p + ((w      ) & 255) * 32);
    __half2 a1 = ldcg_h2(p + ((w >>  8) & 255) * 32);
    __half2 a2 = ldcg_h2(p + ((w >> 16) & 255) * 32);
    __half2 a3 = ldcg_h2(p + ((w >> 24) & 255) * 32);
    float2 f, v;
    f = __half22float2(a0); v.x = b.x * f.x;           v.y = b.x * f.y;
    f = __half22float2(a1); v.x = fmaf(b.y, f.x, v.x); v.y = fmaf(b.y, f.y, v.y);
    f = __half22float2(a2); v.x = fmaf(b.z, f.x, v.x); v.y = fmaf(b.z, f.y, v.y);
    f = __half22float2(a3); v.x = fmaf(b.w, f.x, v.x); v.y = fmaf(b.w, f.y, v.y);
    return v;
}

__global__ void __launch_bounds__(256, 2)
agg_kernel(const float* __restrict__ xin,
           const float* __restrict__ root,
           const float* __restrict__ bias,
           float* __restrict__ xout,
           __half* __restrict__ xout16, int N) {
    __shared__ float sx[8][64];
    int wib  = threadIdx.x >> 5;
    int lane = threadIdx.x & 31;
    int n    = blockIdx.x * 8 + wib;

    for (int t = threadIdx.x; t < 8 * 64; t += 256) {
        int r = t >> 6, c = t & 63;
        int gn = blockIdx.x * 8 + r;
        sx[r][c] = (gn < N) ? xin[(size_t)gn * CDIM + c] : 0.f;
    }
    __syncthreads();
    if (n >= N) return;

    int c0 = lane * 2;
    float2 r2;
    r2.x = bias[c0];
    r2.y = bias[c0 + 1];
    #pragma unroll
    for (int i = 0; i < CDIM; ++i) {
        float  xi = sx[wib][i];
        float2 rv = *(const float2*)&root[i * CDIM + c0];
        r2.x = fmaf(xi, rv.x, r2.x);
        r2.y = fmaf(xi, rv.y, r2.y);
    }

    int beg = g_rowptr[n];
    int end = g_rowptr[n + 1];
    const float NEG = __int_as_float(0xff800000);
    float2 m0 = make_float2(NEG, NEG);
    float2 m1 = make_float2(NEG, NEG);
    float2 m2 = make_float2(NEG, NEG);
    float2 m3 = make_float2(NEG, NEG);
    int e = beg;
    // 8-edge unrolled two-phase: batch all loads, then compute
    for (; e + 7 < end; e += 8) {
        int2   sw[8];
        float4 bb[8];
        #pragma unroll
        for (int j = 0; j < 8; ++j) { sw[j] = g_sw[e + j]; bb[j] = g_basis[e + j]; }
        __half2 h[8][4];
        #pragma unroll
        for (int j = 0; j < 8; ++j) {
            const __half2* p = (const __half2*)(g_xW + (size_t)sw[j].x * KO) + lane;
            unsigned w = (unsigned)sw[j].y;
            h[j][0] = ldcg_h2(p + ((w      ) & 255) * 32);
            h[j][1] = ldcg_h2(p + ((w >>  8) & 255) * 32);
            h[j][2] = ldcg_h2(p + ((w >> 16) & 255) * 32);
            h[j][3] = ldcg_h2(p + ((w >> 24) & 255) * 32);
        }
        #pragma unroll
        for (int j = 0; j < 8; ++j) {
            float4 b = bb[j];
            float2 f, v;
            f = __half22float2(h[j][0]); v.x = b.x * f.x;           v.y = b.x * f.y;
            f = __half22float2(h[j][1]); v.x = fmaf(b.y, f.x, v.x); v.y = fmaf(b.y, f.y, v.y);
            f = __half22float2(h[j][2]); v.x = fmaf(b.z, f.x, v.x); v.y = fmaf(b.z, f.y, v.y);
            f = __half22float2(h[j][3]); v.x = fmaf(b.w, f.x, v.x); v.y = fmaf(b.w, f.y, v.y);
            if ((j & 3) == 0) { m0.x = fmaxf(m0.x, v.x); m0.y = fmaxf(m0.y, v.y); }
            if ((j & 3) == 1) { m1.x = fmaxf(m1.x, v.x); m1.y = fmaxf(m1.y, v.y); }
            if ((j & 3) == 2) { m2.x = fmaxf(m2.x, v.x); m2.y = fmaxf(m2.y, v.y); }
            if ((j & 3) == 3) { m3.x = fmaxf(m3.x, v.x); m3.y = fmaxf(m3.y, v.y); }
        }
    }
    for (; e + 3 < end; e += 4) {
        float2 v0 = edge_msg(e,     lane);
        float2 v1 = edge_msg(e + 1, lane);
        float2 v2 = edge_msg(e + 2, lane);
        float2 v3 = edge_msg(e + 3, lane);
        m0.x = fmaxf(m0.x, v0.x); m0.y = fmaxf(m0.y, v0.y);
        m1.x = fmaxf(m1.x, v1.x); m1.y = fmaxf(m1.y, v1.y);
        m2.x = fmaxf(m2.x, v2.x); m2.y = fmaxf(m2.y, v2.y);
        m3.x = fmaxf(m3.x, v3.x); m3.y = fmaxf(m3.y, v3.y);
    }
    for (; e < end; ++e) {
        float2 v = edge_msg(e, lane);
        m0.x = fmaxf(m0.x, v.x); m0.y = fmaxf(m0.y, v.y);
    }
    float2 m = make_float2(fmaxf(fmaxf(m0.x, m1.x), fmaxf(m2.x, m3.x)),
                           fmaxf(fmaxf(m0.y, m1.y), fmaxf(m2.y, m3.y)));
    float2 agg = (end > beg) ? m : make_float2(0.f, 0.f);
    float2 o = make_float2(fmaxf(agg.x + r2.x, 0.f), fmaxf(agg.y + r2.y, 0.f));
    *(float2*)&xout[(size_t)n * CDIM + c0] = o;
    *(__half2*)&xout16[(size_t)n * CDIM + c0] = __floats2half2_rn(o.x, o.y);
}

// ---------------- final: out = [x | x1 | x2] @ fw + fb ----------------------
__global__ void final_gemm_kernel(const float* __restrict__ x,
                                  const float* __restrict__ fw,
                                  const float* __restrict__ fb,
                                  float* __restrict__ out, int N) {
    __shared__ float2 As2[64][64];
    __shared__ float  Bs[64][64];
    int row0 = blockIdx.x * 128;
    int tid  = threadIdx.x;
    int tx = tid & 7, ty = tid >> 3;

    float2 acc[4][8];
    #pragma unroll
    for (int rp = 0; rp < 4; ++rp)
        #pragma unroll
        for (int c = 0; c < 8; ++c) acc[rp][c] = make_float2(0.f, 0.f);

    for (int ch = 0; ch < 3; ++ch) {
        const float* S = (ch == 0) ? x : (ch == 1) ? g_x1 : g_x2;
        __syncthreads();
        #pragma unroll
        for (int t = tid; t < 128 * 16; t += 128) {
            int r = t >> 4, c4 = (t & 15) * 4;
            int gr = row0 + r;
            float4 v = make_float4(0.f, 0.f, 0.f, 0.f);
            if (gr < N) v = *(const float4*)&S[(size_t)gr * CDIM + c4];
            float* dstp0 = (float*)&As2[r >> 1][c4 + 0];
            int l = r & 1;
            dstp0[l]     = v.x;
            dstp0[2 + l] = v.y;
            dstp0[4 + l] = v.z;
            dstp0[6 + l] = v.w;
        }
        #pragma unroll
        for (int t = tid; t < 64 * 16; t += 128) {
            int r = t >> 4, c4 = (t & 15) * 4;
            *(float4*)&Bs[r][c4] = *(const float4*)&fw[ch * 4096 + r * 64 + c4];
        }
        __syncthreads();

        #pragma unroll 16
        for (int i = 0; i < 64; ++i) {
            float2 ap[4];
            #pragma unroll
            for (int rp = 0; rp < 4; ++rp) ap[rp] = As2[ty * 4 + rp][i];
            float4 b0 = *(const float4*)&Bs[i][tx * 8];
            float4 b1 = *(const float4*)&Bs[i][tx * 8 + 4];
            ull bb[8];
            bb[0] = dup2(b0.x); bb[1] = dup2(b0.y); bb[2] = dup2(b0.z); bb[3] = dup2(b0.w);
            bb[4] = dup2(b1.x); bb[5] = dup2(b1.y); bb[6] = dup2(b1.z); bb[7] = dup2(b1.w);
            #pragma unroll
            for (int rp = 0; rp < 4; ++rp)
                #pragma unroll
                for (int c = 0; c < 8; ++c)
                    acc[rp][c] = ffma2(ap[rp], bb[c], acc[rp][c]);
        }
    }

    float4 fb0 = *(const float4*)&fb[tx * 8];
    float4 fb1 = *(const float4*)&fb[tx * 8 + 4];
    #pragma unroll
    for (int rp = 0; rp < 4; ++rp) {
        int r0 = row0 + ty * 8 + rp * 2;
        if (r0 < N) {
            float4 v0 = make_float4(acc[rp][0].x + fb0.x, acc[rp][1].x + fb0.y,
                                    acc[rp][2].x + fb0.z, acc[rp][3].x + fb0.w);
            float4 v1 = make_float4(acc[rp][4].x + fb1.x, acc[rp][5].x + fb1.y,
                                    acc[rp][6].x + fb1.z, acc[rp][7].x + fb1.w);
            *(float4*)&out[(size_t)r0 * CDIM + tx * 8]     = v0;
            *(float4*)&out[(size_t)r0 * CDIM + tx * 8 + 4] = v1;
        }
        if (r0 + 1 < N) {
            float4 v0 = make_float4(acc[rp][0].y + fb0.x, acc[rp][1].y + fb0.y,
                                    acc[rp][2].y + fb0.z, acc[rp][3].y + fb0.w);
            float4 v1 = make_float4(acc[rp][4].y + fb1.x, acc[rp][5].y + fb1.y,
                                    acc[rp][6].y + fb1.z, acc[rp][7].y + fb1.w);
            *(float4*)&out[(size_t)(r0 + 1) * CDIM + tx * 8]     = v0;
            *(float4*)&out[(size_t)(r0 + 1) * CDIM + tx * 8 + 4] = v1;
        }
    }
}

// ---------------- launch -----------------------------------------------------
extern "C" void kernel_launch(void* const* d_in, const int* in_sizes, int n_in,
                              void* d_out, int out_size) {
    const float* x     = (const float*)d_in[0];
    const int*   ei    = (const int*)  d_in[1];
    const float* attr  = (const float*)d_in[2];
    const float* W1    = (const float*)d_in[3];
    const float* root1 = (const float*)d_in[4];
    const float* b1    = (const float*)d_in[5];
    const float* W2    = (const float*)d_in[6];
    const float* root2 = (const float*)d_in[7];
    const float* b2    = (const float*)d_in[8];
    const float* fw    = (const float*)d_in[9];
    const float* fb    = (const float*)d_in[10];
    float* out = (float*)d_out;

    int N = in_sizes[0] / CDIM;
    int E = in_sizes[1] / 2;
    if (N > MAXN) N = MAXN;
    if (E > MAXE) E = MAXE;

    float *px1 = nullptr, *px2 = nullptr;
    __half *px16 = nullptr, *pw16 = nullptr;
    cudaGetSymbolAddress((void**)&px1, g_x1);
    cudaGetSymbolAddress((void**)&px2, g_x2);
    cudaGetSymbolAddress((void**)&px16, g_x16);
    cudaGetSymbolAddress((void**)&pw16, g_W16);

    int eb = (E + 255) / 256;
    int nb = (N + 255) / 256;
    dim3 ggrid((N + 127) / 128, KK / KBATCH);
    int ab = (N + 7) / 8;

    int xq = N * CDIM / 4;
    int wq = KK * CDIM * CDIM / 4;

    f2h_kernel<<<(xq + 255) / 256, 256>>>(x, px16, xq);        // 1
    f2h_kernel<<<(wq + 255) / 256, 256>>>(W1, pw16, wq);       // 2
    zero_counts_kernel<<<nb, 256>>>(N);                        // 3
    gemm_xw_hmma<<<ggrid, 128>>>(px16, pw16, N);               // 4 <- profiled
    count_kernel<<<eb, 256>>>(ei, E);                          // 5
    scan_kernel<<<1, 1024>>>(N);                               // 6
    scatter_kernel<<<eb, 256>>>(ei, attr, E);                  // 7

    // layer 1 aggregation
    agg_kernel<<<ab, 256>>>(x, root1, b1, px1, px16, N);       // 8

    // layer 2
    f2h_kernel<<<(wq + 255) / 256, 256>>>(W2, pw16, wq);       // 9
    gemm_xw_hmma<<<ggrid, 128>>>(px16, pw16, N);               // 10
    agg_kernel<<<ab, 256>>>(px1, root2, b2, px2, px16, N);     // 11

    // final projection
    final_gemm_kernel<<<(N + 127) / 128, 128>>>(x, fw, fb, out, N);  // 12
}

// round 8
// speedup vs baseline: 1.4329x; 1.2100x over previous
#include <cuda_runtime.h>
#include <cuda_fp16.h>

#define CDIM 64
#define KK   25
#define KO   (CDIM * KK)   // 1600
#define MAXN 50000
#define MAXE 800000

typedef unsigned long long ull;
typedef unsigned int uint32;

// ---------------- scratch (static device globals; no allocation) ------------
__device__ __half g_xW[(size_t)MAXN * KO];   // 160 MB (fp16), reused by both layers
__device__ float  g_x1[(size_t)MAXN * CDIM];
__device__ float  g_x2[(size_t)MAXN * CDIM];
__device__ __half g_x16[(size_t)MAXN * CDIM];  // fp16 input for HMMA gemm
__device__ __half g_W16[KK * CDIM * CDIM];     // fp16 weights for current layer
__device__ int    g_counts[MAXN];
__device__ int    g_rowptr[MAXN + 1];
__device__ int    g_cursor[MAXN];
__device__ int2   g_sw[MAXE];      // {src, packed wi bytes}
__device__ float4 g_basis[MAXE];

// ---------------- packed f32x2 helpers (final gemm) --------------------------
__device__ __forceinline__ float2 ffma2(float2 a, ull b, float2 c) {
    ull au = *reinterpret_cast<ull*>(&a);
    ull cu = *reinterpret_cast<ull*>(&c);
    ull du;
    asm("fma.rn.f32x2 %0, %1, %2, %3;" : "=l"(du) : "l"(au), "l"(b), "l"(cu));
    return *reinterpret_cast<float2*>(&du);
}
__device__ __forceinline__ ull dup2(float b) {
    ull r;
    asm("mov.b64 %0, {%1, %1};" : "=l"(r) : "f"(b));
    return r;
}

// ---------------- mma / ldmatrix helpers -------------------------------------
__device__ __forceinline__ void mma16816(float c[4], const uint32 a[4],
                                         uint32 b0, uint32 b1) {
    asm volatile("mma.sync.aligned.m16n8k16.row.col.f32.f16.f16.f32 "
                 "{%0,%1,%2,%3}, {%4,%5,%6,%7}, {%8,%9}, {%0,%1,%2,%3};"
                 : "+f"(c[0]), "+f"(c[1]), "+f"(c[2]), "+f"(c[3])
                 : "r"(a[0]), "r"(a[1]), "r"(a[2]), "r"(a[3]), "r"(b0), "r"(b1));
}
__device__ __forceinline__ void ldsm_x4(uint32 r[4], uint32 addr) {
    asm volatile("ldmatrix.sync.aligned.m8n8.x4.shared.b16 {%0,%1,%2,%3}, [%4];"
                 : "=r"(r[0]), "=r"(r[1]), "=r"(r[2]), "=r"(r[3]) : "r"(addr));
}
__device__ __forceinline__ void ldsm_x2t(uint32& r0, uint32& r1, uint32 addr) {
    asm volatile("ldmatrix.sync.aligned.m8n8.x2.trans.shared.b16 {%0,%1}, [%2];"
                 : "=r"(r0), "=r"(r1) : "r"(addr));
}

// L2-only half2 load (gathers have no intra-SM reuse)
__device__ __forceinline__ __half2 ldcg_h2(const __half2* p) {
    uint32 v;
    asm volatile("ld.global.cg.b32 %0, [%1];" : "=r"(v) : "l"(p));
    return *reinterpret_cast<__half2*>(&v);
}

// ---------------- fp32 -> fp16 conversion ------------------------------------
__global__ void f2h_kernel(const float* __restrict__ in, __half* __restrict__ out,
                           int n4) {
    int i = blockIdx.x * blockDim.x + threadIdx.x;
    if (i < n4) {
        float4 v = ((const float4*)in)[i];
        union { uint2 u; __half2 h[2]; } pk;
        pk.h[0] = __floats2half2_rn(v.x, v.y);
        pk.h[1] = __floats2half2_rn(v.z, v.w);
        ((uint2*)out)[i] = pk.u;
    }
}

// ---------------- CSR build -------------------------------------------------
__global__ void zero_counts_kernel(int N) {
    int i = blockIdx.x * blockDim.x + threadIdx.x;
    if (i < N) g_counts[i] = 0;
}

__global__ void count_kernel(const int* __restrict__ ei, int E) {
    int e = blockIdx.x * blockDim.x + threadIdx.x;
    if (e < E) atomicAdd(&g_counts[ei[E + e]], 1);
}

__global__ void scan_kernel(int N) {
    __shared__ int warp_off[32];
    __shared__ int s_carry;
    int tid  = threadIdx.x;
    int lane = tid & 31;
    int wid  = tid >> 5;
    if (tid == 0) s_carry = 0;
    __syncthreads();
    for (int base = 0; base < N; base += 1024) {
        int i = base + tid;
        int v = (i < N) ? g_counts[i] : 0;
        int incl = v;
        #pragma unroll
        for (int off = 1; off < 32; off <<= 1) {
            int t = __shfl_up_sync(0xffffffffu, incl, off);
            if (lane >= off) incl += t;
        }
        if (lane == 31) warp_off[wid] = incl;
        __syncthreads();
        if (wid == 0) {
            int s = warp_off[lane];
            int si = s;
            #pragma unroll
            for (int off = 1; off < 32; off <<= 1) {
                int t = __shfl_up_sync(0xffffffffu, si, off);
                if (lane >= off) si += t;
            }
            warp_off[lane] = si - s;
        }
        __syncthreads();
        int excl = incl - v + warp_off[wid] + s_carry;
        if (i < N) { g_rowptr[i] = excl; g_cursor[i] = excl; }
        __syncthreads();
        if (tid == 1023) s_carry = excl + v;
        __syncthreads();
    }
    if (tid == 0) g_rowptr[N] = s_carry;
}

__global__ void scatter_kernel(const int* __restrict__ ei,
                               const float* __restrict__ attr, int E) {
    int e = blockIdx.x * blockDim.x + threadIdx.x;
    if (e >= E) return;
    int src = ei[e];
    int dst = ei[E + e];

    float p0 = attr[2 * e + 0];
    float p1 = attr[2 * e + 1];
    float v0 = p0 * 4.0f, v1 = p1 * 4.0f;
    float l0 = floorf(v0), l1 = floorf(v1);
    float f0 = v0 - l0,    f1 = v1 - l1;
    int i0 = (int)l0, i1 = (int)l1;
    int i00 = min(max(i0, 0), 4);
    int i01 = min(max(i0 + 1, 0), 4);
    int i10 = min(max(i1, 0), 4);
    int i11 = min(max(i1 + 1, 0), 4);

    float4 b;
    b.x = (1.0f - f0) * (1.0f - f1);
    b.y = (1.0f - f0) * f1;
    b.z = f0 * (1.0f - f1);
    b.w = f0 * f1;
    int wp = (i00 + 5 * i10)
           | ((i00 + 5 * i11) << 8)
           | ((i01 + 5 * i10) << 16)
           | ((i01 + 5 * i11) << 24);

    int pos = atomicAdd(&g_cursor[dst], 1);
    g_sw[pos]    = make_int2(src, wp);
    g_basis[pos] = b;
}

// ---------------- HMMA GEMM, k-batched, smem-staged epilogue -----------------
// grid (ceil(N/128), 5): block handles 128 rows x 5 consecutive k's.
// X tile staged once; A fragments register-resident; xs reused as output tile.
#define KBATCH 5
__global__ void __launch_bounds__(128, 4)
gemm_xw_hmma(const __half* __restrict__ X16,
             const __half* __restrict__ W16, int N) {
    __shared__ __half xs[128][72];   // X tile, then reused as output staging
    __shared__ __half ws[64][72];
    int row0 = blockIdx.x * 128;
    int k0   = blockIdx.y * KBATCH;
    int tid  = threadIdx.x;

    // stage X tile (128x64 halfs)
    #pragma unroll
    for (int t = tid; t < 1024; t += 128) {
        int r = t >> 3, c8 = (t & 7) * 8;
        int gr = row0 + r;
        uint4 v = make_uint4(0, 0, 0, 0);
        if (gr < N) v = *(const uint4*)&X16[(size_t)gr * CDIM + c8];
        *(uint4*)&xs[r][c8] = v;
    }
    __syncthreads();

    int warp = tid >> 5, lane = tid & 31;
    int m_base = warp * 32;

    // A fragments: 32 rows x 64 k per warp, loaded ONCE (xs dead afterwards)
    uint32 a[2][4][4];   // [mtile][kstep][frag]
    #pragma unroll
    for (int mt = 0; mt < 2; ++mt)
        #pragma unroll
        for (int kt = 0; kt < 4; ++kt) {
            uint32 addr = (uint32)__cvta_generic_to_shared(
                &xs[m_base + mt * 16 + (lane & 15)][kt * 16 + (lane >> 4) * 8]);
            ldsm_x4(a[mt][kt], addr);
        }
    __syncthreads();   // all warps' A frags loaded before xs is overwritten

    for (int kk = 0; kk < KBATCH; ++kk) {
        int k = k0 + kk;
        __syncthreads();   // prev ws reads + prev xs(out) reads done
        #pragma unroll
        for (int t = tid; t < 512; t += 128) {
            int r = t >> 3, c8 = (t & 7) * 8;
            *(uint4*)&ws[r][c8] = *(const uint4*)&W16[k * 4096 + r * 64 + c8];
        }
        __syncthreads();

        float c[2][8][4];
        #pragma unroll
        for (int mt = 0; mt < 2; ++mt)
            #pragma unroll
            for (int nt = 0; nt < 8; ++nt)
                #pragma unroll
                for (int j = 0; j < 4; ++j) c[mt][nt][j] = 0.f;

        #pragma unroll
        for (int kt = 0; kt < 4; ++kt) {
            #pragma unroll
            for (int nt = 0; nt < 8; ++nt) {
                uint32 baddr = (uint32)__cvta_generic_to_shared(
                    &ws[kt * 16 + (lane & 15)][nt * 8]);
                uint32 b0, b1;
                ldsm_x2t(b0, b1, baddr);
                mma16816(c[0][nt], a[0][kt], b0, b1);
                mma16816(c[1][nt], a[1][kt], b0, b1);
            }
        }

        // epilogue: fragments -> xs rows (warp-local), then coalesced stores
        int fr = lane >> 2;
        int fc = 2 * (lane & 3);
        #pragma unroll
        for (int mt = 0; mt < 2; ++mt) {
            #pragma unroll
            for (int nt = 0; nt < 8; ++nt) {
                *(__half2*)&xs[m_base + mt * 16 + fr][nt * 8 + fc] =
                    __floats2half2_rn(c[mt][nt][0], c[mt][nt][1]);
                *(__half2*)&xs[m_base + mt * 16 + 8 + fr][nt * 8 + fc] =
                    __floats2half2_rn(c[mt][nt][2], c[mt][nt][3]);
            }
        }
        __syncwarp();
        // warp stores its own 32 rows: 4 rows per iter, 128B per row
        #pragma unroll
        for (int it = 0; it < 8; ++it) {
            int r  = m_base + it * 4 + (lane >> 3);
            int gr = row0 + r;
            if (gr < N) {
                uint4 v = *(uint4*)&xs[r][(lane & 7) * 8];
                *(uint4*)&g_xW[(size_t)gr * KO + k * 64 + (lane & 7) * 8] = v;
            }
        }
    }
}

// ---------------- per-node aggregation: warp per node, half2 gathers --------
__device__ __forceinline__ float2 edge_msg(int e, int lane) {
    int2   sw = g_sw[e];
    float4 b  = g_basis[e];
    const __half2* p = (const __half2*)(g_xW + (size_t)sw.x * KO) + lane;
    unsigned w = (unsigned)sw.y;
    __half2 a0 = ldcg_h2(p + ((w      ) & 255) * 32);
    __half2 a1 = ldcg_h2(p + ((w >>  8) & 255) * 32);
    __half2 a2 = ldcg_h2(p + ((w >> 16) & 255) * 32);
    __half2 a3 = ldcg_h2(p + ((w >> 24) & 255) * 32);
    float2 f, v;
    f = __half22float2(a0); v.x = b.x * f.x;           v.y = b.x * f.y;
    f = __half22float2(a1); v.x = fmaf(b.y, f.x, v.x); v.y = fmaf(b.y, f.y, v.y);
    f = __half22float2(a2); v.x = fmaf(b.z, f.x, v.x); v.y = fmaf(b.z, f.y, v.y);
    f = __half22float2(a3); v.x = fmaf(b.w, f.x, v.x); v.y = fmaf(b.w, f.y, v.y);
    return v;
}

__global__ void __launch_bounds__(256, 3)
agg_kernel(const float* __restrict__ xin,
           const float* __restrict__ root,
           const float* __restrict__ bias,
           float* __restrict__ xout,
           __half* __restrict__ xout16, int N) {
    __shared__ float sx[8][64];
    int wib  = threadIdx.x >> 5;
    int lane = threadIdx.x & 31;
    int n    = blockIdx.x * 8 + wib;

    for (int t = threadIdx.x; t < 8 * 64; t += 256) {
        int r = t >> 6, c = t & 63;
        int gn = blockIdx.x * 8 + r;
        sx[r][c] = (gn < N) ? xin[(size_t)gn * CDIM + c] : 0.f;
    }
    __syncthreads();
    if (n >= N) return;

    int c0 = lane * 2;
    float2 r2;
    r2.x = bias[c0];
    r2.y = bias[c0 + 1];
    #pragma unroll
    for (int i = 0; i < CDIM; ++i) {
        float  xi = sx[wib][i];
        float2 rv = *(const float2*)&root[i * CDIM + c0];
        r2.x = fmaf(xi, rv.x, r2.x);
        r2.y = fmaf(xi, rv.y, r2.y);
    }

    int beg = g_rowptr[n];
    int end = g_rowptr[n + 1];
    const float NEG = __int_as_float(0xff800000);
    float2 m0 = make_float2(NEG, NEG);
    float2 m1 = make_float2(NEG, NEG);
    float2 m2 = make_float2(NEG, NEG);
    float2 m3 = make_float2(NEG, NEG);
    int e = beg;
    // 4-edge two-phase batch (lower reg pressure -> 3 blocks/SM)
    for (; e + 3 < end; e += 4) {
        int2   sw[4];
        float4 bb[4];
        #pragma unroll
        for (int j = 0; j < 4; ++j) { sw[j] = g_sw[e + j]; bb[j] = g_basis[e + j]; }
        __half2 h[4][4];
        #pragma unroll
        for (int j = 0; j < 4; ++j) {
            const __half2* p = (const __half2*)(g_xW + (size_t)sw[j].x * KO) + lane;
            unsigned w = (unsigned)sw[j].y;
            h[j][0] = ldcg_h2(p + ((w      ) & 255) * 32);
            h[j][1] = ldcg_h2(p + ((w >>  8) & 255) * 32);
            h[j][2] = ldcg_h2(p + ((w >> 16) & 255) * 32);
            h[j][3] = ldcg_h2(p + ((w >> 24) & 255) * 32);
        }
        #pragma unroll
        for (int j = 0; j < 4; ++j) {
            float4 b = bb[j];
            float2 f, v;
            f = __half22float2(h[j][0]); v.x = b.x * f.x;           v.y = b.x * f.y;
            f = __half22float2(h[j][1]); v.x = fmaf(b.y, f.x, v.x); v.y = fmaf(b.y, f.y, v.y);
            f = __half22float2(h[j][2]); v.x = fmaf(b.z, f.x, v.x); v.y = fmaf(b.z, f.y, v.y);
            f = __half22float2(h[j][3]); v.x = fmaf(b.w, f.x, v.x); v.y = fmaf(b.w, f.y, v.y);
            if (j == 0) { m0.x = fmaxf(m0.x, v.x); m0.y = fmaxf(m0.y, v.y); }
            if (j == 1) { m1.x = fmaxf(m1.x, v.x); m1.y = fmaxf(m1.y, v.y); }
            if (j == 2) { m2.x = fmaxf(m2.x, v.x); m2.y = fmaxf(m2.y, v.y); }
            if (j == 3) { m3.x = fmaxf(m3.x, v.x); m3.y = fmaxf(m3.y, v.y); }
        }
    }
    for (; e < end; ++e) {
        float2 v = edge_msg(e, lane);
        m0.x = fmaxf(m0.x, v.x); m0.y = fmaxf(m0.y, v.y);
    }
    float2 m = make_float2(fmaxf(fmaxf(m0.x, m1.x), fmaxf(m2.x, m3.x)),
                           fmaxf(fmaxf(m0.y, m1.y), fmaxf(m2.y, m3.y)));
    float2 agg = (end > beg) ? m : make_float2(0.f, 0.f);
    float2 o = make_float2(fmaxf(agg.x + r2.x, 0.f), fmaxf(agg.y + r2.y, 0.f));
    *(float2*)&xout[(size_t)n * CDIM + c0] = o;
    *(__half2*)&xout16[(size_t)n * CDIM + c0] = __floats2half2_rn(o.x, o.y);
}

// ---------------- final: out = [x | x1 | x2] @ fw + fb ----------------------
__global__ void final_gemm_kernel(const float* __restrict__ x,
                                  const float* __restrict__ fw,
                                  const float* __restrict__ fb,
                                  float* __restrict__ out, int N) {
    __shared__ float2 As2[64][64];
    __shared__ float  Bs[64][64];
    int row0 = blockIdx.x * 128;
    int tid  = threadIdx.x;
    int tx = tid & 7, ty = tid >> 3;

    float2 acc[4][8];
    #pragma unroll
    for (int rp = 0; rp < 4; ++rp)
        #pragma unroll
        for (int c = 0; c < 8; ++c) acc[rp][c] = make_float2(0.f, 0.f);

    for (int ch = 0; ch < 3; ++ch) {
        const float* S = (ch == 0) ? x : (ch == 1) ? g_x1 : g_x2;
        __syncthreads();
        #pragma unroll
        for (int t = tid; t < 128 * 16; t += 128) {
            int r = t >> 4, c4 = (t & 15) * 4;
            int gr = row0 + r;
            float4 v = make_float4(0.f, 0.f, 0.f, 0.f);
            if (gr < N) v = *(const float4*)&S[(size_t)gr * CDIM + c4];
            float* dstp0 = (float*)&As2[r >> 1][c4 + 0];
            int l = r & 1;
            dstp0[l]     = v.x;
            dstp0[2 + l] = v.y;
            dstp0[4 + l] = v.z;
            dstp0[6 + l] = v.w;
        }
        #pragma unroll
        for (int t = tid; t < 64 * 16; t += 128) {
            int r = t >> 4, c4 = (t & 15) * 4;
            *(float4*)&Bs[r][c4] = *(const float4*)&fw[ch * 4096 + r * 64 + c4];
        }
        __syncthreads();

        #pragma unroll 16
        for (int i = 0; i < 64; ++i) {
            float2 ap[4];
            #pragma unroll
            for (int rp = 0; rp < 4; ++rp) ap[rp] = As2[ty * 4 + rp][i];
            float4 b0 = *(const float4*)&Bs[i][tx * 8];
            float4 b1 = *(const float4*)&Bs[i][tx * 8 + 4];
            ull bb[8];
            bb[0] = dup2(b0.x); bb[1] = dup2(b0.y); bb[2] = dup2(b0.z); bb[3] = dup2(b0.w);
            bb[4] = dup2(b1.x); bb[5] = dup2(b1.y); bb[6] = dup2(b1.z); bb[7] = dup2(b1.w);
            #pragma unroll
            for (int rp = 0; rp < 4; ++rp)
                #pragma unroll
                for (int c = 0; c < 8; ++c)
                    acc[rp][c] = ffma2(ap[rp], bb[c], acc[rp][c]);
        }
    }

    float4 fb0 = *(const float4*)&fb[tx * 8];
    float4 fb1 = *(const float4*)&fb[tx * 8 + 4];
    #pragma unroll
    for (int rp = 0; rp < 4; ++rp) {
        int r0 = row0 + ty * 8 + rp * 2;
        if (r0 < N) {
            float4 v0 = make_float4(acc[rp][0].x + fb0.x, acc[rp][1].x + fb0.y,
                                    acc[rp][2].x + fb0.z, acc[rp][3].x + fb0.w);
            float4 v1 = make_float4(acc[rp][4].x + fb1.x, acc[rp][5].x + fb1.y,
                                    acc[rp][6].x + fb1.z, acc[rp][7].x + fb1.w);
            *(float4*)&out[(size_t)r0 * CDIM + tx * 8]     = v0;
            *(float4*)&out[(size_t)r0 * CDIM + tx * 8 + 4] = v1;
        }
        if (r0 + 1 < N) {
            float4 v0 = make_float4(acc[rp][0].y + fb0.x, acc[rp][1].y + fb0.y,
                                    acc[rp][2].y + fb0.z, acc[rp][3].y + fb0.w);
            float4 v1 = make_float4(acc[rp][4].y + fb1.x, acc[rp][5].y + fb1.y,
                                    acc[rp][6].y + fb1.z, acc[rp][7].y + fb1.w);
            *(float4*)&out[(size_t)(r0 + 1) * CDIM + tx * 8]     = v0;
            *(float4*)&out[(size_t)(r0 + 1) * CDIM + tx * 8 + 4] = v1;
        }
    }
}

// ---------------- launch -----------------------------------------------------
extern "C" void kernel_launch(void* const* d_in, const int* in_sizes, int n_in,
                              void* d_out, int out_size) {
    const float* x     = (const float*)d_in[0];
    const int*   ei    = (const int*)  d_in[1];
    const float* attr  = (const float*)d_in[2];
    const float* W1    = (const float*)d_in[3];
    const float* root1 = (const float*)d_in[4];
    const float* b1    = (const float*)d_in[5];
    const float* W2    = (const float*)d_in[6];
    const float* root2 = (const float*)d_in[7];
    const float* b2    = (const float*)d_in[8];
    const float* fw    = (const float*)d_in[9];
    const float* fb    = (const float*)d_in[10];
    float* out = (float*)d_out;

    int N = in_sizes[0] / CDIM;
    int E = in_sizes[1] / 2;
    if (N > MAXN) N = MAXN;
    if (E > MAXE) E = MAXE;

    float *px1 = nullptr, *px2 = nullptr;
    __half *px16 = nullptr, *pw16 = nullptr;
    cudaGetSymbolAddress((void**)&px1, g_x1);
    cudaGetSymbolAddress((void**)&px2, g_x2);
    cudaGetSymbolAddress((void**)&px16, g_x16);
    cudaGetSymbolAddress((void**)&pw16, g_W16);

    int eb = (E + 255) / 256;
    int nb = (N + 255) / 256;
    dim3 ggrid((N + 127) / 128, KK / KBATCH);
    int ab = (N + 7) / 8;

    int xq = N * CDIM / 4;
    int wq = KK * CDIM * CDIM / 4;

    f2h_kernel<<<(xq + 255) / 256, 256>>>(x, px16, xq);        // 1
    f2h_kernel<<<(wq + 255) / 256, 256>>>(W1, pw16, wq);       // 2
    zero_counts_kernel<<<nb, 256>>>(N);                        // 3
    gemm_xw_hmma<<<ggrid, 128>>>(px16, pw16, N);               // 4 <- profiled
    count_kernel<<<eb, 256>>>(ei, E);                          // 5
    scan_kernel<<<1, 1024>>>(N);                               // 6
    scatter_kernel<<<eb, 256>>>(ei, attr, E);                  // 7

    // layer 1 aggregation
    agg_kernel<<<ab, 256>>>(x, root1, b1, px1, px16, N);       // 8

    // layer 2
    f2h_kernel<<<(wq + 255) / 256, 256>>>(W2, pw16, wq);       // 9
    gemm_xw_hmma<<<ggrid, 128>>>(px16, pw16, N);               // 10
    agg_kernel<<<ab, 256>>>(px1, root2, b2, px2, px16, N);     // 11

    // final projection
    final_gemm_kernel<<<(N + 127) / 128, 128>>>(x, fw, fb, out, N);  // 12
}